// round 11
// baseline (speedup 1.0000x reference)
#include <cuda_runtime.h>
#include <cuda_bf16.h>
#include <cstdint>

// Detector post-process: persistent blocks, per-WARP independent depth-2
// TMA-bulk pipelines (no block-wide sync in main loop). Each warp owns an
// 8-box slice of every 64-box tile with its own mbarrier + stage slice.
//
// Output (flat float32): [box_out (B*4) | probs (B) | class_index (B)]

#ifndef THRESHOLD
#define THRESHOLD 0.5f
#endif

#define TB 256                 // 8 warps
#define NWARP 8
#define BOXES 64               // boxes per tile (8 per warp)
#define WBOXES 8               // boxes per warp slice
#define WSC 2560               // 8 * 320 score bytes
#define WBX_OFF 2560           // box region in slice (128 B)
#define WCF_OFF 2688           // conf region in slice (32 B)
#define WSTAGE 2720            // slice bytes (16B multiple)
#define DEPTH 2

__device__ __forceinline__ uint32_t s2u32(const void* p) {
    return (uint32_t)__cvta_generic_to_shared(p);
}
__device__ __forceinline__ void mbar_init(uint32_t mb, uint32_t cnt) {
    asm volatile("mbarrier.init.shared.b64 [%0], %1;" :: "r"(mb), "r"(cnt) : "memory");
}
__device__ __forceinline__ void mbar_expect_tx(uint32_t mb, uint32_t bytes) {
    asm volatile("mbarrier.arrive.expect_tx.shared.b64 _, [%0], %1;"
                 :: "r"(mb), "r"(bytes) : "memory");
}
__device__ __forceinline__ void bulk_g2s(uint32_t sdst, const void* gsrc,
                                         uint32_t bytes, uint32_t mb) {
    asm volatile(
        "cp.async.bulk.shared::cta.global.mbarrier::complete_tx::bytes "
        "[%0], [%1], %2, [%3];"
        :: "r"(sdst), "l"(gsrc), "r"(bytes), "r"(mb) : "memory");
}
// try_wait with HW suspend-time hint: sleeping poll.
__device__ __forceinline__ void mbar_wait(uint32_t mb, uint32_t ph) {
    asm volatile(
        "{\n\t.reg .pred P;\n\t"
        "W%=:\n\t"
        "mbarrier.try_wait.parity.acquire.cta.shared::cta.b64 P, [%0], %1, 0x989680;\n\t"
        "@!P bra W%=;\n\t"
        "}"
        :: "r"(mb), "r"(ph) : "memory");
}

__global__ __launch_bounds__(TB) void detector_kernel(
    const float4* __restrict__ box,
    const float*  __restrict__ conf,
    const float4* __restrict__ score4,     // [B*20]
    const float4* __restrict__ prior,
    const unsigned* __restrict__ feat_raw,
    float4* __restrict__ box_out,
    float*  __restrict__ probs_out,
    float*  __restrict__ cls_out,
    int n_boxes, int prior_mod, int n_full_tiles)
{
    __shared__ __align__(128) char ring[DEPTH][NWARP][WSTAGE];  // 43520 B
    __shared__ unsigned long long mbar[DEPTH][NWARP];

    const int t    = threadIdx.x;
    const int w    = t >> 5;       // warp id (0..7)
    const int lane = t & 31;
    const int bw   = lane >> 2;    // box within warp slice (0..7)
    const int q    = lane & 3;     // quarter of the 80 classes

    if (t == 0) {
        #pragma unroll
        for (int d = 0; d < DEPTH; d++)
            #pragma unroll
            for (int ww = 0; ww < NWARP; ww++)
                mbar_init(s2u32(&mbar[d][ww]), 1);
        asm volatile("fence.proxy.async.shared::cta;" ::: "memory");
    }
    __syncthreads();   // only block-wide sync: after mbarrier init

    // feat_size may arrive as int32 or float32 bits; decode robustly.
    unsigned fb = *feat_raw;
    float feat = (fb < 0x01000000u) ? (float)fb : __uint_as_float(fb);
    float inv_feat = 1.0f / feat;

    // per-warp slice prefetch: lane 0 issues 3 bulk copies for its 8 boxes
    auto prefetch_w = [&](int tile, int st) {
        if (lane == 0 && tile < n_full_tiles) {
            int box0 = tile * BOXES + w * WBOXES;
            uint32_t sb = s2u32(&ring[st][w][0]);
            uint32_t mb = s2u32(&mbar[st][w]);
            mbar_expect_tx(mb, WSTAGE);
            bulk_g2s(sb,           (const char*)score4 + (size_t)box0 * 320,
                     WSC, mb);
            bulk_g2s(sb + WBX_OFF, box  + box0, WBOXES * 16, mb);
            bulk_g2s(sb + WCF_OFF, conf + box0, WBOXES * 4,  mb);
        }
    };

    int tile = blockIdx.x;
    const int stride = gridDim.x;

    prefetch_w(tile, 0);
    prefetch_w(tile + stride, 1);

    int idx = 0;
    for (; tile < n_full_tiles; tile += stride, idx++) {
        const int bf = idx & 1;
        const int ph = (idx >> 1) & 1;

        mbar_wait(s2u32(&mbar[bf][w]), ph);   // this warp's slice only

        const char* sl = &ring[bf][w][0];
        const int i = tile * BOXES + w * WBOXES + bw;
        {
            const float4* s = (const float4*)(sl + bw * 320) + q * 5;
            const float c = ((const float*)(sl + WCF_OFF))[bw];
            float best = -3.402823466e+38f;
            int bidx = 0;
            #pragma unroll
            for (int j = 0; j < 5; j++) {
                float4 v = s[j];
                float p0 = c * v.x, p1 = c * v.y, p2 = c * v.z, p3 = c * v.w;
                int base = (q * 5 + j) * 4;
                if (p0 > best) { best = p0; bidx = base;     }
                if (p1 > best) { best = p1; bidx = base + 1; }
                if (p2 > best) { best = p2; bidx = base + 2; }
                if (p3 > best) { best = p3; bidx = base + 3; }
            }
            // pack: non-negative fp32 bits monotonic; low byte favors smaller
            // class on exact ties (matches jnp.argmax first occurrence).
            unsigned long long pk =
                ((unsigned long long)__float_as_uint(best) << 32) |
                (unsigned)(127 - bidx);
            unsigned long long o1 = __shfl_xor_sync(0xFFFFFFFFu, pk, 1, 4);
            if (o1 > pk) pk = o1;
            unsigned long long o2 = __shfl_xor_sync(0xFFFFFFFFu, pk, 2, 4);
            if (o2 > pk) pk = o2;

            if (q == 0 && i < n_boxes) {
                float prob = __uint_as_float((unsigned)(pk >> 32));
                int cls = 127 - (int)(pk & 0xFFu);

                float4 b4 = ((const float4*)(sl + WBX_OFF))[bw];
                float4 p  = prior[i % prior_mod];
                float cx = b4.x + p.x;
                float cy = b4.y + p.y;
                float hw = 0.5f * (b4.z * p.z);
                float hh = 0.5f * (b4.w * p.w);

                float4 corners;
                corners.x = (cx - hw) * inv_feat;
                corners.y = (cy - hh) * inv_feat;
                corners.z = (cx + hw) * inv_feat;
                corners.w = (cy + hh) * inv_feat;

                bool m = prob > THRESHOLD;
                box_out[i]   = m ? corners : make_float4(0.f, 0.f, 0.f, 0.f);
                probs_out[i] = m ? prob : 0.0f;
                cls_out[i]   = (float)cls;
            }
        }
        __syncwarp();                          // reconverge, slice consumed
        prefetch_w(tile + 2 * stride, bf);     // re-arm our slice (tile i+2)
    }

    // ---- tail boxes (n_boxes not multiple of BOXES): direct GMEM path ----
    int tail0 = n_full_tiles * BOXES;
    if (blockIdx.x == 0 && tail0 < n_boxes) {
        int bx = t >> 2;                  // reuse 4-threads-per-box layout
        int i = tail0 + bx;
        if (i < n_boxes) {
            float c = conf[i];
            const float4* s = score4 + (size_t)i * 20 + q * 5;
            float best = -3.402823466e+38f;
            int bidx = 0;
            #pragma unroll
            for (int j = 0; j < 5; j++) {
                float4 v = s[j];
                float p0 = c * v.x, p1 = c * v.y, p2 = c * v.z, p3 = c * v.w;
                int base = (q * 5 + j) * 4;
                if (p0 > best) { best = p0; bidx = base;     }
                if (p1 > best) { best = p1; bidx = base + 1; }
                if (p2 > best) { best = p2; bidx = base + 2; }
                if (p3 > best) { best = p3; bidx = base + 3; }
            }
            unsigned long long pk =
                ((unsigned long long)__float_as_uint(best) << 32) |
                (unsigned)(127 - bidx);
            unsigned long long o1 = __shfl_xor_sync(0xFFFFFFFFu, pk, 1, 4);
            if (o1 > pk) pk = o1;
            unsigned long long o2 = __shfl_xor_sync(0xFFFFFFFFu, pk, 2, 4);
            if (o2 > pk) pk = o2;
            if (q == 0) {
                float prob = __uint_as_float((unsigned)(pk >> 32));
                int cls = 127 - (int)(pk & 0xFFu);
                float4 b4 = box[i];
                float4 p  = prior[i % prior_mod];
                float cx = b4.x + p.x, cy = b4.y + p.y;
                float hw = 0.5f * (b4.z * p.z), hh = 0.5f * (b4.w * p.w);
                float4 corners;
                corners.x = (cx - hw) * inv_feat;
                corners.y = (cy - hh) * inv_feat;
                corners.z = (cx + hw) * inv_feat;
                corners.w = (cy + hh) * inv_feat;
                bool m = prob > THRESHOLD;
                box_out[i]   = m ? corners : make_float4(0.f, 0.f, 0.f, 0.f);
                probs_out[i] = m ? prob : 0.0f;
                cls_out[i]   = (float)cls;
            }
        }
    }
}

extern "C" void kernel_launch(void* const* d_in, const int* in_sizes, int n_in,
                              void* d_out, int out_size)
{
    const float4*   box    = (const float4*)d_in[0];
    const float*    conf   = (const float*)d_in[1];
    const float4*   score4 = (const float4*)d_in[2];
    const float4*   prior  = (const float4*)d_in[3];
    const unsigned* feat   = (const unsigned*)d_in[4];

    int n_boxes      = in_sizes[1];       // N*HW*A
    int prior_mod    = in_sizes[3] / 4;   // HW*A
    int n_full_tiles = n_boxes / BOXES;

    float* out       = (float*)d_out;
    float4* box_out  = (float4*)out;
    float*  probs    = out + (size_t)n_boxes * 4;
    float*  cls      = out + (size_t)n_boxes * 5;

    int blocks = 148 * 5;                 // persistent, 5 blocks/SM (43.5 KB)
    if (blocks > n_full_tiles) blocks = n_full_tiles > 0 ? n_full_tiles : 1;

    detector_kernel<<<blocks, TB>>>(box, conf, score4, prior, feat,
                                    box_out, probs, cls,
                                    n_boxes, prior_mod, n_full_tiles);
}

// round 12
// speedup vs baseline: 1.0062x; 1.0062x over previous
#include <cuda_runtime.h>
#include <cuda_bf16.h>
#include <cstdint>

// Detector post-process: persistent blocks, depth-2 TMA-bulk ring, 64-box
// tiles split into two independently-signaled 32-box halves, 4-threads-per-box
// packed-shuffle argmax, streaming (evict-first) output stores.
//
// Output (flat float32): [box_out (B*4) | probs (B) | class_index (B)]

#ifndef THRESHOLD
#define THRESHOLD 0.5f
#endif

#define TB 256                    // threads per block (4 per box)
#define BOXES 64                  // boxes per tile
#define HBOXES 32                 // boxes per half
#define HSC_BYTES (HBOXES * 320)  // 10240 score bytes per half
#define HBX_OFF HSC_BYTES         // box region offset within half (512 B)
#define HCF_OFF (HSC_BYTES + 512) // conf region offset within half (128 B)
#define HALF_BYTES (HSC_BYTES + 512 + 128)   // 10880
#define DEPTH 2

__device__ __forceinline__ uint32_t s2u32(const void* p) {
    return (uint32_t)__cvta_generic_to_shared(p);
}
__device__ __forceinline__ void mbar_init(uint32_t mb, uint32_t cnt) {
    asm volatile("mbarrier.init.shared.b64 [%0], %1;" :: "r"(mb), "r"(cnt) : "memory");
}
__device__ __forceinline__ void mbar_expect_tx(uint32_t mb, uint32_t bytes) {
    asm volatile("mbarrier.arrive.expect_tx.shared.b64 _, [%0], %1;"
                 :: "r"(mb), "r"(bytes) : "memory");
}
__device__ __forceinline__ void bulk_g2s(uint32_t sdst, const void* gsrc,
                                         uint32_t bytes, uint32_t mb) {
    asm volatile(
        "cp.async.bulk.shared::cta.global.mbarrier::complete_tx::bytes "
        "[%0], [%1], %2, [%3];"
        :: "r"(sdst), "l"(gsrc), "r"(bytes), "r"(mb) : "memory");
}
// try_wait with HW suspend-time hint: sleeping poll, no issue-slot burn.
__device__ __forceinline__ void mbar_wait(uint32_t mb, uint32_t ph) {
    asm volatile(
        "{\n\t.reg .pred P;\n\t"
        "W%=:\n\t"
        "mbarrier.try_wait.parity.acquire.cta.shared::cta.b64 P, [%0], %1, 0x989680;\n\t"
        "@!P bra W%=;\n\t"
        "}"
        :: "r"(mb), "r"(ph) : "memory");
}

__global__ __launch_bounds__(TB) void detector_kernel(
    const float4* __restrict__ box,
    const float*  __restrict__ conf,
    const float4* __restrict__ score4,     // [B*20]
    const float4* __restrict__ prior,
    const unsigned* __restrict__ feat_raw,
    float4* __restrict__ box_out,
    float*  __restrict__ probs_out,
    float*  __restrict__ cls_out,
    int n_boxes, int prior_mod, int n_full_tiles)
{
    __shared__ __align__(128) char ring[DEPTH][2][HALF_BYTES];  // 43520 B
    __shared__ unsigned long long mbar[DEPTH][2];

    const int t = threadIdx.x;

    if (t == 0) {
        #pragma unroll
        for (int d = 0; d < DEPTH; d++) {
            mbar_init(s2u32(&mbar[d][0]), 1);
            mbar_init(s2u32(&mbar[d][1]), 1);
        }
        asm volatile("fence.proxy.async.shared::cta;" ::: "memory");
    }
    __syncthreads();

    // feat_size may arrive as int32 or float32 bits; decode robustly.
    unsigned fb = *feat_raw;
    float feat = (fb < 0x01000000u) ? (float)fb : __uint_as_float(fb);
    float inv_feat = 1.0f / feat;

    auto prefetch = [&](int tile, int st) {
        if (t == 0 && tile < n_full_tiles) {
            #pragma unroll
            for (int h = 0; h < 2; h++) {
                uint32_t sb = s2u32(&ring[st][h][0]);
                uint32_t mb = s2u32(&mbar[st][h]);
                int box0 = tile * BOXES + h * HBOXES;
                const char* sc_src = (const char*)score4 + (size_t)box0 * 320;
                mbar_expect_tx(mb, HALF_BYTES);
                bulk_g2s(sb,           sc_src,      HSC_BYTES,    mb);
                bulk_g2s(sb + HBX_OFF, box  + box0, HBOXES * 16,  mb);
                bulk_g2s(sb + HCF_OFF, conf + box0, HBOXES * 4,   mb);
            }
        }
    };

    int tile = blockIdx.x;
    const int stride = gridDim.x;

    prefetch(tile, 0);

    const int bx  = t >> 2;        // box within tile (0..63)
    const int q   = t & 3;         // quarter of the 80 classes
    const int hlf = bx >> 5;       // which half this thread consumes
    const int bxh = bx & 31;       // box within half

    int idx = 0;
    for (; tile < n_full_tiles; tile += stride, idx++) {
        const int bf = idx & 1;
        const int ph = (idx >> 1) & 1;

        prefetch(tile + stride, bf ^ 1);
        mbar_wait(s2u32(&mbar[bf][hlf]), ph);   // wait only on our half

        // ---- compute: 4 threads per box, 5 float4 slots each ----
        const int i = tile * BOXES + bx;
        {
            const char* hb = &ring[bf][hlf][0];
            const float4* s = (const float4*)hb + bxh * 20 + q * 5;
            const float c = ((const float*)(hb + HCF_OFF))[bxh];
            float best = -3.402823466e+38f;
            int bidx = 0;
            #pragma unroll
            for (int j = 0; j < 5; j++) {
                float4 v = s[j];
                float p0 = c * v.x, p1 = c * v.y, p2 = c * v.z, p3 = c * v.w;
                int base = (q * 5 + j) * 4;
                if (p0 > best) { best = p0; bidx = base;     }
                if (p1 > best) { best = p1; bidx = base + 1; }
                if (p2 > best) { best = p2; bidx = base + 2; }
                if (p3 > best) { best = p3; bidx = base + 3; }
            }
            // pack: non-negative fp32 bits monotonic; low byte favors smaller
            // class on exact ties (matches jnp.argmax first occurrence).
            unsigned long long pk =
                ((unsigned long long)__float_as_uint(best) << 32) |
                (unsigned)(127 - bidx);
            unsigned long long o1 = __shfl_xor_sync(0xFFFFFFFFu, pk, 1, 4);
            if (o1 > pk) pk = o1;
            unsigned long long o2 = __shfl_xor_sync(0xFFFFFFFFu, pk, 2, 4);
            if (o2 > pk) pk = o2;

            if (q == 0) {
                float prob = __uint_as_float((unsigned)(pk >> 32));
                int cls = 127 - (int)(pk & 0xFFu);

                float4 b4 = ((const float4*)(hb + HBX_OFF))[bxh];
                float4 p  = prior[i % prior_mod];
                float cx = b4.x + p.x;
                float cy = b4.y + p.y;
                float hw = 0.5f * (b4.z * p.z);
                float hh = 0.5f * (b4.w * p.w);

                float4 corners;
                corners.x = (cx - hw) * inv_feat;
                corners.y = (cy - hh) * inv_feat;
                corners.z = (cx + hw) * inv_feat;
                corners.w = (cy + hh) * inv_feat;

                bool m = prob > THRESHOLD;
                float4 obox = m ? corners : make_float4(0.f, 0.f, 0.f, 0.f);
                // streaming (evict-first) stores: outputs are never re-read,
                // keep them from displacing the score stream in L2.
                __stcs(&box_out[i], obox);
                __stcs(&probs_out[i], m ? prob : 0.0f);
                __stcs(&cls_out[i], (float)cls);
            }
        }
        __syncthreads();   // both halves consumed before stage is re-armed
    }

    // ---- tail boxes (n_boxes not multiple of BOXES): direct GMEM path ----
    int tail0 = n_full_tiles * BOXES;
    if (blockIdx.x == 0 && tail0 < n_boxes) {
        int i = tail0 + bx;
        if (i < n_boxes) {
            float c = conf[i];
            const float4* s = score4 + (size_t)i * 20 + q * 5;
            float best = -3.402823466e+38f;
            int bidx = 0;
            #pragma unroll
            for (int j = 0; j < 5; j++) {
                float4 v = s[j];
                float p0 = c * v.x, p1 = c * v.y, p2 = c * v.z, p3 = c * v.w;
                int base = (q * 5 + j) * 4;
                if (p0 > best) { best = p0; bidx = base;     }
                if (p1 > best) { best = p1; bidx = base + 1; }
                if (p2 > best) { best = p2; bidx = base + 2; }
                if (p3 > best) { best = p3; bidx = base + 3; }
            }
            unsigned long long pk =
                ((unsigned long long)__float_as_uint(best) << 32) |
                (unsigned)(127 - bidx);
            unsigned long long o1 = __shfl_xor_sync(0xFFFFFFFFu, pk, 1, 4);
            if (o1 > pk) pk = o1;
            unsigned long long o2 = __shfl_xor_sync(0xFFFFFFFFu, pk, 2, 4);
            if (o2 > pk) pk = o2;
            if (q == 0) {
                float prob = __uint_as_float((unsigned)(pk >> 32));
                int cls = 127 - (int)(pk & 0xFFu);
                float4 b4 = box[i];
                float4 p  = prior[i % prior_mod];
                float cx = b4.x + p.x, cy = b4.y + p.y;
                float hw = 0.5f * (b4.z * p.z), hh = 0.5f * (b4.w * p.w);
                float4 corners;
                corners.x = (cx - hw) * inv_feat;
                corners.y = (cy - hh) * inv_feat;
                corners.z = (cx + hw) * inv_feat;
                corners.w = (cy + hh) * inv_feat;
                bool m = prob > THRESHOLD;
                box_out[i]   = m ? corners : make_float4(0.f, 0.f, 0.f, 0.f);
                probs_out[i] = m ? prob : 0.0f;
                cls_out[i]   = (float)cls;
            }
        }
    }
}

extern "C" void kernel_launch(void* const* d_in, const int* in_sizes, int n_in,
                              void* d_out, int out_size)
{
    const float4*   box    = (const float4*)d_in[0];
    const float*    conf   = (const float*)d_in[1];
    const float4*   score4 = (const float4*)d_in[2];
    const float4*   prior  = (const float4*)d_in[3];
    const unsigned* feat   = (const unsigned*)d_in[4];

    int n_boxes      = in_sizes[1];       // N*HW*A
    int prior_mod    = in_sizes[3] / 4;   // HW*A
    int n_full_tiles = n_boxes / BOXES;

    float* out       = (float*)d_out;
    float4* box_out  = (float4*)out;
    float*  probs    = out + (size_t)n_boxes * 4;
    float*  cls      = out + (size_t)n_boxes * 5;

    int blocks = 148 * 5;                 // persistent, 5 blocks/SM (43.5 KB)
    if (blocks > n_full_tiles) blocks = n_full_tiles > 0 ? n_full_tiles : 1;

    detector_kernel<<<blocks, TB>>>(box, conf, score4, prior, feat,
                                    box_out, probs, cls,
                                    n_boxes, prior_mod, n_full_tiles);
}